// round 15
// baseline (speedup 1.0000x reference)
#include <cuda_runtime.h>
#include <math.h>

// ---------------- problem constants ----------------
#define BQ 32
#define H 2048
#define NH 32
#define NKV 8
#define HD 64
#define GQ 4
#define INTER 8192
#define NBLK 256
#define BSZ 16
#define NSPLIT 8
#define SPLIT_LEN 512

typedef unsigned long long ull;

#define FFMA2(d, a, b, c) \
    asm("fma.rn.f32x2 %0, %1, %2, %3;" : "=l"(d) : "l"(a), "l"(b), "l"(c))

#define CP8(dst, src) \
    asm volatile("cp.async.ca.shared.global [%0], [%1], 8;" :: "r"(dst), "l"(src))
#define CP_COMMIT() asm volatile("cp.async.commit_group;")
#define CP_WAIT2()  asm volatile("cp.async.wait_group 2;" ::: "memory")

// one 8-k chunk (2-col variant; expects smA, acc in scope; smA row stride 64)
#define FFMA_CHUNK64(kk0, wbuf)                                                      \
    _Pragma("unroll")                                                                \
    for (int b = 0; b < 32; b++) {                                                   \
        const ulonglong2* ap = reinterpret_cast<const ulonglong2*>(&smA[b * 64 + (kk0)]); \
        ulonglong2 a01 = ap[0], a23 = ap[1], a45 = ap[2], a67 = ap[3];               \
        FFMA2(acc[b], a01.x, wbuf[0], acc[b]);                                       \
        FFMA2(acc[b], a01.y, wbuf[1], acc[b]);                                       \
        FFMA2(acc[b], a23.x, wbuf[2], acc[b]);                                       \
        FFMA2(acc[b], a23.y, wbuf[3], acc[b]);                                       \
        FFMA2(acc[b], a45.x, wbuf[4], acc[b]);                                       \
        FFMA2(acc[b], a45.y, wbuf[5], acc[b]);                                       \
        FFMA2(acc[b], a67.x, wbuf[6], acc[b]);                                       \
        FFMA2(acc[b], a67.y, wbuf[7], acc[b]);                                       \
    }

// Single-tile pipeline (KC=64, 8 chunks), proven.
// Expects: smA loaded+synced, Wj, n in scope.
#define GEMM_PIPE_BODY(NCHUNK)                                                       \
    unsigned wsm[4];                                                                 \
    _Pragma("unroll")                                                                \
    for (int s = 0; s < 4; s++)                                                      \
        wsm[s] = (unsigned)__cvta_generic_to_shared(&smW[s][0][2 * t]);              \
    _Pragma("unroll")                                                                \
    for (int c = 0; c < 3; c++) {                                                    \
        _Pragma("unroll")                                                            \
        for (int r = 0; r < 8; r++)                                                  \
            CP8(wsm[c] + r * 1024, Wj + (size_t)(c * 8 + r) * n);                    \
        CP_COMMIT();                                                                 \
    }                                                                                \
    ull acc[32];                                                                     \
    _Pragma("unroll")                                                                \
    for (int b = 0; b < 32; b++) acc[b] = 0ull;                                      \
    _Pragma("unroll")                                                                \
    for (int c = 0; c < NCHUNK; c++) {                                               \
        CP_WAIT2();                                                                  \
        ull w[8];                                                                    \
        const float* wp = &smW[c & 3][0][2 * t];                                     \
        _Pragma("unroll")                                                            \
        for (int r = 0; r < 8; r++)                                                  \
            w[r] = *reinterpret_cast<const ull*>(wp + r * 256);                      \
        FFMA_CHUNK64(c * 8, w)                                                       \
        if (c + 3 < NCHUNK) {                                                        \
            _Pragma("unroll")                                                        \
            for (int r = 0; r < 8; r++)                                              \
                CP8(wsm[(c + 3) & 3] + r * 1024, Wj + (size_t)((c + 3) * 8 + r) * n);\
            CP_COMMIT();                                                             \
        } else {                                                                     \
            CP_COMMIT();                                                             \
        }                                                                            \
    }

// Two-tile pipeline (KC=128, 16 chunks, ALL offsets static).
// Weight ring runs continuously across the tile boundary; smA reloaded once.
// Expects: smA loaded for tile0 (kbase), A/lda/kbase, Wj, n in scope.
#define GEMM_PIPE_BODY_2T                                                            \
    unsigned wsm[4];                                                                 \
    _Pragma("unroll")                                                                \
    for (int s = 0; s < 4; s++)                                                      \
        wsm[s] = (unsigned)__cvta_generic_to_shared(&smW[s][0][2 * t]);              \
    _Pragma("unroll")                                                                \
    for (int c = 0; c < 3; c++) {                                                    \
        _Pragma("unroll")                                                            \
        for (int r = 0; r < 8; r++)                                                  \
            CP8(wsm[c] + r * 1024, Wj + (size_t)(c * 8 + r) * n);                    \
        CP_COMMIT();                                                                 \
    }                                                                                \
    ull acc[32];                                                                     \
    _Pragma("unroll")                                                                \
    for (int b = 0; b < 32; b++) acc[b] = 0ull;                                      \
    _Pragma("unroll")                                                                \
    for (int c = 0; c < 8; c++) {                                                    \
        CP_WAIT2();                                                                  \
        ull w[8];                                                                    \
        const float* wp = &smW[c & 3][0][2 * t];                                     \
        _Pragma("unroll")                                                            \
        for (int r = 0; r < 8; r++)                                                  \
            w[r] = *reinterpret_cast<const ull*>(wp + r * 256);                      \
        FFMA_CHUNK64(c * 8, w)                                                       \
        _Pragma("unroll")                                                            \
        for (int r = 0; r < 8; r++)                                                  \
            CP8(wsm[(c + 3) & 3] + r * 1024, Wj + (size_t)((c + 3) * 8 + r) * n);    \
        CP_COMMIT();                                                                 \
    }                                                                                \
    __syncthreads();                                                                 \
    _Pragma("unroll")                                                                \
    for (int i = t; i < 2048; i += 128) {                                            \
        int b = i >> 6, kk = i & 63;                                                 \
        unsigned r = __float_as_uint(A[b * lda + kbase + 64 + kk]);                  \
        smA[i] = (ull)r | ((ull)r << 32);                                            \
    }                                                                                \
    __syncthreads();                                                                 \
    _Pragma("unroll")                                                                \
    for (int c = 8; c < 16; c++) {                                                   \
        CP_WAIT2();                                                                  \
        ull w[8];                                                                    \
        const float* wp = &smW[c & 3][0][2 * t];                                     \
        _Pragma("unroll")                                                            \
        for (int r = 0; r < 8; r++)                                                  \
            w[r] = *reinterpret_cast<const ull*>(wp + r * 256);                      \
        FFMA_CHUNK64((c - 8) * 8, w)                                                 \
        if (c + 3 < 16) {                                                            \
            _Pragma("unroll")                                                        \
            for (int r = 0; r < 8; r++)                                              \
                CP8(wsm[(c + 3) & 3] + r * 1024, Wj + (size_t)((c + 3) * 8 + r) * n);\
            CP_COMMIT();                                                             \
        } else {                                                                     \
            CP_COMMIT();                                                             \
        }                                                                            \
    }

// ---------------- scratch ----------------
__device__ float g_normed[BQ * H];
__device__ float g_qkv[BQ * 3072];       // q[2048] | k[512] | v[512]
__device__ float g_attn[BQ * H];
__device__ float g_x1[BQ * H];
__device__ float g_n2[BQ * H];
__device__ float g_act[BQ * INTER];
__device__ float g_pacc[BQ * NKV * NSPLIT * GQ * HD];
__device__ float g_pl[BQ * NKV * NSPLIT * GQ];
__device__ float p_qkv[32 * BQ * 3072];
__device__ float p_o[32 * BQ * 2048];
__device__ float p_g[16 * BQ * INTER];
__device__ float p_u[16 * BQ * INTER];
__device__ float p_d[64 * BQ * 2048];

// ---------------- RMSNorm ----------------
__global__ __launch_bounds__(256) void rmsnorm_kernel(
    const float* __restrict__ x, const float* __restrict__ w, float* __restrict__ o)
{
    int b = blockIdx.x, t = threadIdx.x;
    const float* xr = x + b * H;
    float ss = 0.f;
    for (int i = t; i < H; i += 256) { float v = xr[i]; ss += v * v; }
    __shared__ float red[256];
    red[t] = ss; __syncthreads();
    for (int s = 128; s > 0; s >>= 1) {
        if (t < s) red[t] += red[t + s];
        __syncthreads();
    }
    float inv = rsqrtf(red[0] / (float)H + 1e-5f);
    for (int i = t; i < H; i += 256) o[b * H + i] = xr[i] * inv * w[i];
}

// ---------------- 2-col cp.async GEMM partial, KC=64 (o-proj) ----------------
__global__ __launch_bounds__(128) void gemm_async(
    const float* __restrict__ A, int lda,
    const float* __restrict__ W, int n,
    float* __restrict__ P)
{
    __shared__ ull smA[32 * 64];
    __shared__ float smW[4][8][256];
    int t = threadIdx.x;
    int j = blockIdx.x * 256 + 2 * t;
    int kbase = blockIdx.y * 64;

#pragma unroll
    for (int i = t; i < 2048; i += 128) {
        int b = i >> 6, kk = i & 63;
        unsigned r = __float_as_uint(A[b * lda + kbase + kk]);
        smA[i] = (ull)r | ((ull)r << 32);
    }
    __syncthreads();

    const float* Wj = W + (size_t)kbase * n + j;
    GEMM_PIPE_BODY(8)

    float* Pp = P + (size_t)blockIdx.y * (32 * n);
#pragma unroll
    for (int b = 0; b < 32; b++) {
        float2 v;
        v.x = __uint_as_float((unsigned)acc[b]);
        v.y = __uint_as_float((unsigned)(acc[b] >> 32));
        *reinterpret_cast<float2*>(&Pp[b * n + j]) = v;
    }
}

// ---------------- 2-col KC=128 two-tile GEMM partial (down proj) ----------------
// grid (n/256, K/128). acc carried across both 64-tiles.
__global__ __launch_bounds__(128) void gemm_async2(
    const float* __restrict__ A, int lda,
    const float* __restrict__ W, int n,
    float* __restrict__ P)
{
    __shared__ ull smA[32 * 64];
    __shared__ float smW[4][8][256];
    int t = threadIdx.x;
    int j = blockIdx.x * 256 + 2 * t;
    int kbase = blockIdx.y * 128;

#pragma unroll
    for (int i = t; i < 2048; i += 128) {
        int b = i >> 6, kk = i & 63;
        unsigned r = __float_as_uint(A[b * lda + kbase + kk]);
        smA[i] = (ull)r | ((ull)r << 32);
    }
    __syncthreads();

    const float* Wj = W + (size_t)kbase * n + j;
    GEMM_PIPE_BODY_2T

    float* Pp = P + (size_t)blockIdx.y * (32 * n);
#pragma unroll
    for (int b = 0; b < 32; b++) {
        float2 v;
        v.x = __uint_as_float((unsigned)acc[b]);
        v.y = __uint_as_float((unsigned)(acc[b] >> 32));
        *reinterpret_cast<float2*>(&Pp[b * n + j]) = v;
    }
}

// ---------------- fused gate+up KC=128 two-tile partial (one launch) ----------------
// grid (64, 16): x<32 -> gate into p_g, else up into p_u. n = INTER.
__global__ __launch_bounds__(128) void gu_async2(
    const float* __restrict__ gw, const float* __restrict__ uw)
{
    __shared__ ull smA[32 * 64];
    __shared__ float smW[4][8][256];
    int t = threadIdx.x;
    int bx = blockIdx.x;
    const float* W;
    float* P;
    int jb;
    if (bx < 32) { W = gw; P = p_g; jb = bx * 256; }
    else         { W = uw; P = p_u; jb = (bx - 32) * 256; }
    int j = jb + 2 * t;
    const int n = INTER;
    const float* A = g_n2;
    const int lda = H;
    int kbase = blockIdx.y * 128;

#pragma unroll
    for (int i = t; i < 2048; i += 128) {
        int b = i >> 6, kk = i & 63;
        unsigned r = __float_as_uint(A[b * lda + kbase + kk]);
        smA[i] = (ull)r | ((ull)r << 32);
    }
    __syncthreads();

    const float* Wj = W + (size_t)kbase * n + j;
    GEMM_PIPE_BODY_2T

    float* Pp = P + (size_t)blockIdx.y * (32 * n);
#pragma unroll
    for (int b = 0; b < 32; b++) {
        float2 v;
        v.x = __uint_as_float((unsigned)acc[b]);
        v.y = __uint_as_float((unsigned)(acc[b] >> 32));
        *reinterpret_cast<float2*>(&Pp[b * n + j]) = v;
    }
}

// ---------------- QKV fused async partial (q/k/v segments), KC=64 ----------------
__global__ __launch_bounds__(128) void qkv_async(
    const float* __restrict__ qw, const float* __restrict__ kw, const float* __restrict__ vw)
{
    __shared__ ull smA[32 * 64];
    __shared__ float smW[4][8][256];
    int t = threadIdx.x;
    int j0 = blockIdx.x * 256;
    int kbase = blockIdx.y * 64;
    const float* W; int n; int jl;
    if (j0 < 2048)      { W = qw; n = 2048; jl = j0; }
    else if (j0 < 2560) { W = kw; n = 512;  jl = j0 - 2048; }
    else                { W = vw; n = 512;  jl = j0 - 2560; }
    jl += 2 * t;

#pragma unroll
    for (int i = t; i < 2048; i += 128) {
        int b = i >> 6, kk = i & 63;
        unsigned r = __float_as_uint(g_normed[b * H + kbase + kk]);
        smA[i] = (ull)r | ((ull)r << 32);
    }
    __syncthreads();

    const float* Wj = W + (size_t)kbase * n + jl;
    GEMM_PIPE_BODY(8)

    float* P = p_qkv + (size_t)blockIdx.y * (32 * 3072);
#pragma unroll
    for (int b = 0; b < 32; b++) {
        float2 v;
        v.x = __uint_as_float((unsigned)acc[b]);
        v.y = __uint_as_float((unsigned)(acc[b] >> 32));
        *reinterpret_cast<float2*>(&P[b * 3072 + j0 + 2 * t]) = v;
    }
}

// ---------------- fused QKV reduce + RoPE (32 partials) ----------------
__global__ __launch_bounds__(256) void qkv_reduce_rope(const int* __restrict__ sl)
{
    int idx = blockIdx.x * 256 + threadIdx.x;
    int b = idx / 1536, slot = idx - b * 1536;
    if (slot < 1280) {
        int head = slot >> 5, i = slot & 31;
        int col1 = (head < 32) ? head * 64 + i : 2048 + (head - 32) * 64 + i;
        int col2 = col1 + 32;
        float x1 = 0.f, x2 = 0.f;
#pragma unroll 4
        for (int s = 0; s < 32; s++) {
            const float* P = p_qkv + (size_t)s * (32 * 3072) + b * 3072;
            x1 += P[col1]; x2 += P[col2];
        }
        float pos = (float)sl[b];
        float inv = expf(-(float)i * (9.210340371976184f / 32.f));
        float ang = pos * inv;
        float sn, cs; sincosf(ang, &sn, &cs);
        g_qkv[b * 3072 + col1] = x1 * cs - x2 * sn;
        g_qkv[b * 3072 + col2] = x2 * cs + x1 * sn;
    } else {
        int col = 2560 + (slot - 1280) * 2;
        float a = 0.f, c = 0.f;
#pragma unroll 4
        for (int s = 0; s < 32; s++) {
            const float* P = p_qkv + (size_t)s * (32 * 3072) + b * 3072;
            a += P[col]; c += P[col + 1];
        }
        g_qkv[b * 3072 + col] = a;
        g_qkv[b * 3072 + col + 1] = c;
    }
}

// ---------------- reduces ----------------
__global__ void reduce_kernel(const float* __restrict__ P, int total, int KS,
                              const float* __restrict__ res, float* __restrict__ out)
{
    int i = blockIdx.x * 256 + threadIdx.x;
    if (i >= total) return;
    float v = res ? res[i] : 0.f;
#pragma unroll 8
    for (int s = 0; s < KS; s++) v += P[(size_t)s * total + i];
    out[i] = v;
}

__global__ void gu_reduce_kernel()
{
    int i = blockIdx.x * 256 + threadIdx.x;
    const int total = BQ * INTER;
    float gv = 0.f, uv = 0.f;
#pragma unroll 8
    for (int s = 0; s < 16; s++) {
        gv += p_g[(size_t)s * total + i];
        uv += p_u[(size_t)s * total + i];
    }
    g_act[i] = gv * (1.f / (1.f + __expf(-gv))) * uv;
}

// ---------------- split-KV decode attention (smem bt, fixed-ref softmax, 2x unroll) ----
__global__ __launch_bounds__(128) void attn_kernel(
    const float* __restrict__ kc, const float* __restrict__ vc,
    const int* __restrict__ bt, const int* __restrict__ sl)
{
    int sp = blockIdx.x, kvh = blockIdx.y, b = blockIdx.z;
    int tid = threadIdx.x, wid = tid >> 5, lane = tid & 31;
    int dc = lane & 7, tok = lane >> 3;
    int seqlen = sl[b];
    int total = seqlen + 1;
    int start = sp * SPLIT_LEN;
    int end = min(start + SPLIT_LEN, total);

    __shared__ int s_bt[SPLIT_LEN / BSZ];   // 32 block entries for this split
    if (tid < SPLIT_LEN / BSZ)
        s_bt[tid] = bt[b * NBLK + sp * (SPLIT_LEN / BSZ) + tid];
    __syncthreads();
    int btbase = sp * (SPLIT_LEN / BSZ);

    float4 qa[GQ], qb[GQ];
#pragma unroll
    for (int g = 0; g < GQ; g++) {
        const float* qp = g_qkv + b * 3072 + (kvh * GQ + g) * HD + dc * 8;
        float4 a = *reinterpret_cast<const float4*>(qp);
        float4 c = *reinterpret_cast<const float4*>(qp + 4);
        a.x *= 0.125f; a.y *= 0.125f; a.z *= 0.125f; a.w *= 0.125f;
        c.x *= 0.125f; c.y *= 0.125f; c.z *= 0.125f; c.w *= 0.125f;
        qa[g] = a; qb[g] = c;
    }
    float l[GQ], acc[GQ][8];
#pragma unroll
    for (int g = 0; g < GQ; g++) {
        l[g] = 0.f;
#pragma unroll
        for (int d = 0; d < 8; d++) acc[g][d] = 0.f;
    }

    for (int s0 = start + wid * 4; s0 < end; s0 += 32) {
        int sA = s0 + tok;
        int sB = s0 + 16 + tok;
        bool vA = sA < end, vB = sB < end;
        float4 kaA = {0,0,0,0}, kbA = {0,0,0,0}, vaA = {0,0,0,0}, vbA = {0,0,0,0};
        float4 kaB = {0,0,0,0}, kbB = {0,0,0,0}, vaB = {0,0,0,0}, vbB = {0,0,0,0};
        if (vA) {
            const float *kp, *vp;
            if (sA == seqlen) {
                kp = g_qkv + b * 3072 + 2048 + kvh * HD;
                vp = kp + 512;
            } else {
                int blk = s_bt[(sA >> 4) - btbase];
                int off = ((blk * BSZ + (sA & 15)) * NKV + kvh) * HD;
                kp = kc + off; vp = vc + off;
            }
            kaA = *reinterpret_cast<const float4*>(kp + dc * 8);
            kbA = *reinterpret_cast<const float4*>(kp + dc * 8 + 4);
            vaA = *reinterpret_cast<const float4*>(vp + dc * 8);
            vbA = *reinterpret_cast<const float4*>(vp + dc * 8 + 4);
        }
        if (vB) {
            const float *kp, *vp;
            if (sB == seqlen) {
                kp = g_qkv + b * 3072 + 2048 + kvh * HD;
                vp = kp + 512;
            } else {
                int blk = s_bt[(sB >> 4) - btbase];
                int off = ((blk * BSZ + (sB & 15)) * NKV + kvh) * HD;
                kp = kc + off; vp = vc + off;
            }
            kaB = *reinterpret_cast<const float4*>(kp + dc * 8);
            kbB = *reinterpret_cast<const float4*>(kp + dc * 8 + 4);
            vaB = *reinterpret_cast<const float4*>(vp + dc * 8);
            vbB = *reinterpret_cast<const float4*>(vp + dc * 8 + 4);
        }
        float scA[GQ], scB[GQ];
#pragma unroll
        for (int g = 0; g < GQ; g++) {
            scA[g] = qa[g].x * kaA.x + qa[g].y * kaA.y + qa[g].z * kaA.z + qa[g].w * kaA.w
                   + qb[g].x * kbA.x + qb[g].y * kbA.y + qb[g].z * kbA.z + qb[g].w * kbA.w;
            scB[g] = qa[g].x * kaB.x + qa[g].y * kaB.y + qa[g].z * kaB.z + qa[g].w * kaB.w
                   + qb[g].x * kbB.x + qb[g].y * kbB.y + qb[g].z * kbB.z + qb[g].w * kbB.w;
        }
#pragma unroll
        for (int o = 1; o <= 4; o <<= 1) {
#pragma unroll
            for (int g = 0; g < GQ; g++) {
                scA[g] += __shfl_xor_sync(0xffffffffu, scA[g], o);
                scB[g] += __shfl_xor_sync(0xffffffffu, scB[g], o);
            }
        }
#pragma unroll
        for (int g = 0; g < GQ; g++) {
            float pA = vA ? __expf(fminf(scA[g], 75.f)) : 0.f;
            float pB = vB ? __expf(fminf(scB[g], 75.f)) : 0.f;
            l[g] += pA + pB;
            acc[g][0] += pA * vaA.x + pB * vaB.x;
            acc[g][1] += pA * vaA.y + pB * vaB.y;
            acc[g][2] += pA * vaA.z + pB * vaB.z;
            acc[g][3] += pA * vaA.w + pB * vaB.w;
            acc[g][4] += pA * vbA.x + pB * vbB.x;
            acc[g][5] += pA * vbA.y + pB * vbB.y;
            acc[g][6] += pA * vbA.z + pB * vbB.z;
            acc[g][7] += pA * vbA.w + pB * vbB.w;
        }
    }

#pragma unroll
    for (int o = 8; o <= 16; o <<= 1) {
#pragma unroll
        for (int g = 0; g < GQ; g++) {
#pragma unroll
            for (int d = 0; d < 8; d++)
                acc[g][d] += __shfl_xor_sync(0xffffffffu, acc[g][d], o);
            l[g] += __shfl_xor_sync(0xffffffffu, l[g], o);
        }
    }

    __shared__ float s_l[4][GQ], s_acc[4][GQ][HD];
    if (tok == 0) {
#pragma unroll
        for (int g = 0; g < GQ; g++)
#pragma unroll
            for (int d = 0; d < 8; d++) s_acc[wid][g][dc * 8 + d] = acc[g][d];
    }
    if (lane == 0) {
#pragma unroll
        for (int g = 0; g < GQ; g++) s_l[wid][g] = l[g];
    }
    __syncthreads();
    int pidx = (b * NKV + kvh) * NSPLIT + sp;
    for (int p = tid; p < GQ * HD; p += 128) {
        int g = p >> 6, d = p & 63;
        float L = s_l[0][g] + s_l[1][g] + s_l[2][g] + s_l[3][g];
        float A = s_acc[0][g][d] + s_acc[1][g][d] + s_acc[2][g][d] + s_acc[3][g][d];
        g_pacc[pidx * 256 + p] = A;
        if (d == 0) g_pl[pidx * GQ + g] = L;
    }
}

__global__ __launch_bounds__(256) void attn_combine_kernel()
{
    int bk = blockIdx.x;
    int t = threadIdx.x;
    int g = t >> 6, d = t & 63;
    float L = 0.f, A = 0.f;
#pragma unroll
    for (int sp = 0; sp < NSPLIT; sp++) {
        L += g_pl[(bk * NSPLIT + sp) * GQ + g];
        A += g_pacc[(bk * NSPLIT + sp) * 256 + t];
    }
    int b = bk >> 3, kvh = bk & 7;
    g_attn[b * H + (kvh * GQ + g) * HD + d] = A / L;
}

// ---------------- launcher ----------------
static float* sym(const void* s) { void* p = nullptr; cudaGetSymbolAddress(&p, s); return (float*)p; }

extern "C" void kernel_launch(void* const* d_in, const int* in_sizes, int n_in,
                              void* d_out, int out_size)
{
    const float* x   = (const float*)d_in[0];
    const float* kc  = (const float*)d_in[1];
    const float* vc  = (const float*)d_in[2];
    const float* ln1 = (const float*)d_in[3];
    const float* qw  = (const float*)d_in[4];
    const float* kw  = (const float*)d_in[5];
    const float* vw  = (const float*)d_in[6];
    const float* ow  = (const float*)d_in[7];
    const float* ln2 = (const float*)d_in[8];
    const float* gw  = (const float*)d_in[9];
    const float* uw  = (const float*)d_in[10];
    const float* dw  = (const float*)d_in[11];
    const int*   bt  = (const int*)d_in[12];
    const int*   sl  = (const int*)d_in[13];
    float* out = (float*)d_out;

    float* a_normed = sym(g_normed);
    float* a_attn   = sym(g_attn);
    float* a_x1     = sym(g_x1);
    float* a_n2     = sym(g_n2);
    float* a_act    = sym(g_act);
    float* a_po     = sym(p_o);
    float* a_pd     = sym(p_d);

    // 1. RMSNorm 1
    rmsnorm_kernel<<<BQ, 256>>>(x, ln1, a_normed);
    // 2. QKV projection (async pipeline, 32 k-splits) + reduce w/ RoPE
    qkv_async<<<dim3(12, 32), 128>>>(qw, kw, vw);
    qkv_reduce_rope<<<192, 256>>>(sl);
    // 3. split-KV attention (8 splits)
    attn_kernel<<<dim3(NSPLIT, NKV, BQ), 128>>>(kc, vc, bt, sl);
    attn_combine_kernel<<<BQ * NKV, 256>>>();
    // 4. O projection + residual (KC=64, 256 blocks)
    gemm_async<<<dim3(8, 32), 128>>>(a_attn, H, ow, H, a_po);
    reduce_kernel<<<(BQ * H) / 256, 256>>>(a_po, BQ * H, 32, x, a_x1);
    // 5. RMSNorm 2
    rmsnorm_kernel<<<BQ, 256>>>(a_x1, ln2, a_n2);
    // 6. gate + up fused, KC=128 two-tile (16 splits, 1024 blocks), then SiLU
    gu_async2<<<dim3(64, 16), 128>>>(gw, uw);
    gu_reduce_kernel<<<(BQ * INTER) / 256, 256>>>();
    // 7. down projection KC=128 two-tile (64 splits, 512 blocks) + residual -> out
    gemm_async2<<<dim3(8, 64), 128>>>(a_act, INTER, dw, H, a_pd);
    reduce_kernel<<<(BQ * H) / 256, 256>>>(a_pd, BQ * H, 64, a_x1, out);
}

// round 16
// speedup vs baseline: 1.6776x; 1.6776x over previous
#include <cuda_runtime.h>
#include <math.h>

// ---------------- problem constants ----------------
#define BQ 32
#define H 2048
#define NH 32
#define NKV 8
#define HD 64
#define GQ 4
#define INTER 8192
#define NBLK 256
#define BSZ 16
#define NSPLIT 8
#define SPLIT_LEN 512

typedef unsigned long long ull;

#define FFMA2(d, a, b, c) \
    asm("fma.rn.f32x2 %0, %1, %2, %3;" : "=l"(d) : "l"(a), "l"(b), "l"(c))

#define CP8(dst, src) \
    asm volatile("cp.async.ca.shared.global [%0], [%1], 8;" :: "r"(dst), "l"(src))
#define CP_COMMIT() asm volatile("cp.async.commit_group;")
#define CP_WAIT2()  asm volatile("cp.async.wait_group 2;" ::: "memory")

// one 8-k chunk (2-col variant; expects smA, acc in scope; KC=64)
#define FFMA_CHUNK64(kk0, wbuf)                                                      \
    _Pragma("unroll")                                                                \
    for (int b = 0; b < 32; b++) {                                                   \
        const ulonglong2* ap = reinterpret_cast<const ulonglong2*>(&smA[b * 64 + (kk0)]); \
        ulonglong2 a01 = ap[0], a23 = ap[1], a45 = ap[2], a67 = ap[3];               \
        FFMA2(acc[b], a01.x, wbuf[0], acc[b]);                                       \
        FFMA2(acc[b], a01.y, wbuf[1], acc[b]);                                       \
        FFMA2(acc[b], a23.x, wbuf[2], acc[b]);                                       \
        FFMA2(acc[b], a23.y, wbuf[3], acc[b]);                                       \
        FFMA2(acc[b], a45.x, wbuf[4], acc[b]);                                       \
        FFMA2(acc[b], a45.y, wbuf[5], acc[b]);                                       \
        FFMA2(acc[b], a67.x, wbuf[6], acc[b]);                                       \
        FFMA2(acc[b], a67.y, wbuf[7], acc[b]);                                       \
    }

// GEMM inner pipeline (4-stage cp.async ring), shared by all 2-col GEMM kernels.
// Expects: smA loaded+synced, Wj points at this thread's first weight, n = row stride.
#define GEMM_PIPE_BODY(NCHUNK)                                                       \
    unsigned wsm[4];                                                                 \
    _Pragma("unroll")                                                                \
    for (int s = 0; s < 4; s++)                                                      \
        wsm[s] = (unsigned)__cvta_generic_to_shared(&smW[s][0][2 * t]);              \
    _Pragma("unroll")                                                                \
    for (int c = 0; c < 3; c++) {                                                    \
        _Pragma("unroll")                                                            \
        for (int r = 0; r < 8; r++)                                                  \
            CP8(wsm[c] + r * 1024, Wj + (size_t)(c * 8 + r) * n);                    \
        CP_COMMIT();                                                                 \
    }                                                                                \
    ull acc[32];                                                                     \
    _Pragma("unroll")                                                                \
    for (int b = 0; b < 32; b++) acc[b] = 0ull;                                      \
    _Pragma("unroll")                                                                \
    for (int c = 0; c < NCHUNK; c++) {                                               \
        CP_WAIT2();                                                                  \
        ull w[8];                                                                    \
        const float* wp = &smW[c & 3][0][2 * t];                                     \
        _Pragma("unroll")                                                            \
        for (int r = 0; r < 8; r++)                                                  \
            w[r] = *reinterpret_cast<const ull*>(wp + r * 256);                      \
        FFMA_CHUNK64(c * 8, w)                                                       \
        if (c + 3 < NCHUNK) {                                                        \
            _Pragma("unroll")                                                        \
            for (int r = 0; r < 8; r++)                                              \
                CP8(wsm[(c + 3) & 3] + r * 1024, Wj + (size_t)((c + 3) * 8 + r) * n);\
            CP_COMMIT();                                                             \
        } else {                                                                     \
            CP_COMMIT();                                                             \
        }                                                                            \
    }

// ---------------- scratch ----------------
__device__ float g_normed[BQ * H];
__device__ float g_qkv[BQ * 3072];       // q[2048] | k[512] | v[512]
__device__ float g_attn[BQ * H];
__device__ float g_x1[BQ * H];
__device__ float g_n2[BQ * H];
__device__ float g_act[BQ * INTER];
__device__ float g_pacc[BQ * NKV * NSPLIT * GQ * HD];
__device__ float g_pl[BQ * NKV * NSPLIT * GQ];
__device__ float p_qkv[32 * BQ * 3072];
__device__ float p_o[32 * BQ * 2048];
__device__ float p_g[32 * BQ * INTER];
__device__ float p_u[32 * BQ * INTER];
__device__ float p_d[128 * BQ * 2048];

// ---------------- RMSNorm ----------------
__global__ __launch_bounds__(256) void rmsnorm_kernel(
    const float* __restrict__ x, const float* __restrict__ w, float* __restrict__ o)
{
    int b = blockIdx.x, t = threadIdx.x;
    const float* xr = x + b * H;
    float ss = 0.f;
    for (int i = t; i < H; i += 256) { float v = xr[i]; ss += v * v; }
    __shared__ float red[256];
    red[t] = ss; __syncthreads();
    for (int s = 128; s > 0; s >>= 1) {
        if (t < s) red[t] += red[t + s];
        __syncthreads();
    }
    float inv = rsqrtf(red[0] / (float)H + 1e-5f);
    for (int i = t; i < H; i += 256) o[b * H + i] = xr[i] * inv * w[i];
}

// ---------------- 2-col cp.async GEMM partial, KC=64 ----------------
__global__ __launch_bounds__(128) void gemm_async(
    const float* __restrict__ A, int lda,
    const float* __restrict__ W, int n,
    float* __restrict__ P)
{
    __shared__ ull smA[32 * 64];
    __shared__ float smW[4][8][256];
    int t = threadIdx.x;
    int j = blockIdx.x * 256 + 2 * t;
    int kbase = blockIdx.y * 64;

#pragma unroll
    for (int i = t; i < 2048; i += 128) {
        int b = i >> 6, kk = i & 63;
        unsigned r = __float_as_uint(A[b * lda + kbase + kk]);
        smA[i] = (ull)r | ((ull)r << 32);
    }
    __syncthreads();

    const float* Wj = W + (size_t)kbase * n + j;
    GEMM_PIPE_BODY(8)

    float* Pp = P + (size_t)blockIdx.y * (32 * n);
#pragma unroll
    for (int b = 0; b < 32; b++) {
        float2 v;
        v.x = __uint_as_float((unsigned)acc[b]);
        v.y = __uint_as_float((unsigned)(acc[b] >> 32));
        *reinterpret_cast<float2*>(&Pp[b * n + j]) = v;
    }
}

// ---------------- fused gate+up GEMM partial (one launch) ----------------
// grid (64, 32): x<32 -> gate into p_g, else up into p_u. n = INTER.
__global__ __launch_bounds__(128) void gu_async(
    const float* __restrict__ gw, const float* __restrict__ uw)
{
    __shared__ ull smA[32 * 64];
    __shared__ float smW[4][8][256];
    int t = threadIdx.x;
    int bx = blockIdx.x;
    const float* W;
    float* P;
    int jb;
    if (bx < 32) { W = gw; P = p_g; jb = bx * 256; }
    else         { W = uw; P = p_u; jb = (bx - 32) * 256; }
    int j = jb + 2 * t;
    const int n = INTER;
    int kbase = blockIdx.y * 64;

#pragma unroll
    for (int i = t; i < 2048; i += 128) {
        int b = i >> 6, kk = i & 63;
        unsigned r = __float_as_uint(g_n2[b * H + kbase + kk]);
        smA[i] = (ull)r | ((ull)r << 32);
    }
    __syncthreads();

    const float* Wj = W + (size_t)kbase * n + j;
    GEMM_PIPE_BODY(8)

    float* Pp = P + (size_t)blockIdx.y * (32 * n);
#pragma unroll
    for (int b = 0; b < 32; b++) {
        float2 v;
        v.x = __uint_as_float((unsigned)acc[b]);
        v.y = __uint_as_float((unsigned)(acc[b] >> 32));
        *reinterpret_cast<float2*>(&Pp[b * n + j]) = v;
    }
}

// ---------------- QKV fused async partial (q/k/v segments), KC=64 ----------------
__global__ __launch_bounds__(128) void qkv_async(
    const float* __restrict__ qw, const float* __restrict__ kw, const float* __restrict__ vw)
{
    __shared__ ull smA[32 * 64];
    __shared__ float smW[4][8][256];
    int t = threadIdx.x;
    int j0 = blockIdx.x * 256;
    int kbase = blockIdx.y * 64;
    const float* W; int n; int jl;
    if (j0 < 2048)      { W = qw; n = 2048; jl = j0; }
    else if (j0 < 2560) { W = kw; n = 512;  jl = j0 - 2048; }
    else                { W = vw; n = 512;  jl = j0 - 2560; }
    jl += 2 * t;

#pragma unroll
    for (int i = t; i < 2048; i += 128) {
        int b = i >> 6, kk = i & 63;
        unsigned r = __float_as_uint(g_normed[b * H + kbase + kk]);
        smA[i] = (ull)r | ((ull)r << 32);
    }
    __syncthreads();

    const float* Wj = W + (size_t)kbase * n + jl;
    GEMM_PIPE_BODY(8)

    float* P = p_qkv + (size_t)blockIdx.y * (32 * 3072);
#pragma unroll
    for (int b = 0; b < 32; b++) {
        float2 v;
        v.x = __uint_as_float((unsigned)acc[b]);
        v.y = __uint_as_float((unsigned)(acc[b] >> 32));
        *reinterpret_cast<float2*>(&P[b * 3072 + j0 + 2 * t]) = v;
    }
}

// ---------------- fused QKV reduce + RoPE (32 partials) ----------------
__global__ __launch_bounds__(256) void qkv_reduce_rope(const int* __restrict__ sl)
{
    int idx = blockIdx.x * 256 + threadIdx.x;
    int b = idx / 1536, slot = idx - b * 1536;
    if (slot < 1280) {
        int head = slot >> 5, i = slot & 31;
        int col1 = (head < 32) ? head * 64 + i : 2048 + (head - 32) * 64 + i;
        int col2 = col1 + 32;
        float x1 = 0.f, x2 = 0.f;
#pragma unroll 4
        for (int s = 0; s < 32; s++) {
            const float* P = p_qkv + (size_t)s * (32 * 3072) + b * 3072;
            x1 += P[col1]; x2 += P[col2];
        }
        float pos = (float)sl[b];
        float inv = expf(-(float)i * (9.210340371976184f / 32.f));
        float ang = pos * inv;
        float sn, cs; sincosf(ang, &sn, &cs);
        g_qkv[b * 3072 + col1] = x1 * cs - x2 * sn;
        g_qkv[b * 3072 + col2] = x2 * cs + x1 * sn;
    } else {
        int col = 2560 + (slot - 1280) * 2;
        float a = 0.f, c = 0.f;
#pragma unroll 4
        for (int s = 0; s < 32; s++) {
            const float* P = p_qkv + (size_t)s * (32 * 3072) + b * 3072;
            a += P[col]; c += P[col + 1];
        }
        g_qkv[b * 3072 + col] = a;
        g_qkv[b * 3072 + col + 1] = c;
    }
}

// ---------------- reduces ----------------
__global__ void reduce_kernel(const float* __restrict__ P, int total, int KS,
                              const float* __restrict__ res, float* __restrict__ out)
{
    int i = blockIdx.x * 256 + threadIdx.x;
    if (i >= total) return;
    float v = res ? res[i] : 0.f;
#pragma unroll 8
    for (int s = 0; s < KS; s++) v += P[(size_t)s * total + i];
    out[i] = v;
}

__global__ void gu_reduce_kernel()
{
    int i = blockIdx.x * 256 + threadIdx.x;
    const int total = BQ * INTER;
    float gv = 0.f, uv = 0.f;
#pragma unroll 8
    for (int s = 0; s < 32; s++) {
        gv += p_g[(size_t)s * total + i];
        uv += p_u[(size_t)s * total + i];
    }
    g_act[i] = gv * (1.f / (1.f + __expf(-gv))) * uv;
}

// ---------------- split-KV decode attention (smem bt, fixed-ref softmax, 2x unroll) ----
__global__ __launch_bounds__(128) void attn_kernel(
    const float* __restrict__ kc, const float* __restrict__ vc,
    const int* __restrict__ bt, const int* __restrict__ sl)
{
    int sp = blockIdx.x, kvh = blockIdx.y, b = blockIdx.z;
    int tid = threadIdx.x, wid = tid >> 5, lane = tid & 31;
    int dc = lane & 7, tok = lane >> 3;
    int seqlen = sl[b];
    int total = seqlen + 1;
    int start = sp * SPLIT_LEN;
    int end = min(start + SPLIT_LEN, total);

    __shared__ int s_bt[SPLIT_LEN / BSZ];   // 32 block entries for this split
    if (tid < SPLIT_LEN / BSZ)
        s_bt[tid] = bt[b * NBLK + sp * (SPLIT_LEN / BSZ) + tid];
    __syncthreads();
    int btbase = sp * (SPLIT_LEN / BSZ);

    float4 qa[GQ], qb[GQ];
#pragma unroll
    for (int g = 0; g < GQ; g++) {
        const float* qp = g_qkv + b * 3072 + (kvh * GQ + g) * HD + dc * 8;
        float4 a = *reinterpret_cast<const float4*>(qp);
        float4 c = *reinterpret_cast<const float4*>(qp + 4);
        a.x *= 0.125f; a.y *= 0.125f; a.z *= 0.125f; a.w *= 0.125f;
        c.x *= 0.125f; c.y *= 0.125f; c.z *= 0.125f; c.w *= 0.125f;
        qa[g] = a; qb[g] = c;
    }
    float l[GQ], acc[GQ][8];
#pragma unroll
    for (int g = 0; g < GQ; g++) {
        l[g] = 0.f;
#pragma unroll
        for (int d = 0; d < 8; d++) acc[g][d] = 0.f;
    }

    for (int s0 = start + wid * 4; s0 < end; s0 += 32) {
        int sA = s0 + tok;
        int sB = s0 + 16 + tok;
        bool vA = sA < end, vB = sB < end;
        float4 kaA = {0,0,0,0}, kbA = {0,0,0,0}, vaA = {0,0,0,0}, vbA = {0,0,0,0};
        float4 kaB = {0,0,0,0}, kbB = {0,0,0,0}, vaB = {0,0,0,0}, vbB = {0,0,0,0};
        if (vA) {
            const float *kp, *vp;
            if (sA == seqlen) {
                kp = g_qkv + b * 3072 + 2048 + kvh * HD;
                vp = kp + 512;
            } else {
                int blk = s_bt[(sA >> 4) - btbase];
                int off = ((blk * BSZ + (sA & 15)) * NKV + kvh) * HD;
                kp = kc + off; vp = vc + off;
            }
            kaA = *reinterpret_cast<const float4*>(kp + dc * 8);
            kbA = *reinterpret_cast<const float4*>(kp + dc * 8 + 4);
            vaA = *reinterpret_cast<const float4*>(vp + dc * 8);
            vbA = *reinterpret_cast<const float4*>(vp + dc * 8 + 4);
        }
        if (vB) {
            const float *kp, *vp;
            if (sB == seqlen) {
                kp = g_qkv + b * 3072 + 2048 + kvh * HD;
                vp = kp + 512;
            } else {
                int blk = s_bt[(sB >> 4) - btbase];
                int off = ((blk * BSZ + (sB & 15)) * NKV + kvh) * HD;
                kp = kc + off; vp = vc + off;
            }
            kaB = *reinterpret_cast<const float4*>(kp + dc * 8);
            kbB = *reinterpret_cast<const float4*>(kp + dc * 8 + 4);
            vaB = *reinterpret_cast<const float4*>(vp + dc * 8);
            vbB = *reinterpret_cast<const float4*>(vp + dc * 8 + 4);
        }
        float scA[GQ], scB[GQ];
#pragma unroll
        for (int g = 0; g < GQ; g++) {
            scA[g] = qa[g].x * kaA.x + qa[g].y * kaA.y + qa[g].z * kaA.z + qa[g].w * kaA.w
                   + qb[g].x * kbA.x + qb[g].y * kbA.y + qb[g].z * kbA.z + qb[g].w * kbA.w;
            scB[g] = qa[g].x * kaB.x + qa[g].y * kaB.y + qa[g].z * kaB.z + qa[g].w * kaB.w
                   + qb[g].x * kbB.x + qb[g].y * kbB.y + qb[g].z * kbB.z + qb[g].w * kbB.w;
        }
#pragma unroll
        for (int o = 1; o <= 4; o <<= 1) {
#pragma unroll
            for (int g = 0; g < GQ; g++) {
                scA[g] += __shfl_xor_sync(0xffffffffu, scA[g], o);
                scB[g] += __shfl_xor_sync(0xffffffffu, scB[g], o);
            }
        }
#pragma unroll
        for (int g = 0; g < GQ; g++) {
            float pA = vA ? __expf(fminf(scA[g], 75.f)) : 0.f;
            float pB = vB ? __expf(fminf(scB[g], 75.f)) : 0.f;
            l[g] += pA + pB;
            acc[g][0] += pA * vaA.x + pB * vaB.x;
            acc[g][1] += pA * vaA.y + pB * vaB.y;
            acc[g][2] += pA * vaA.z + pB * vaB.z;
            acc[g][3] += pA * vaA.w + pB * vaB.w;
            acc[g][4] += pA * vbA.x + pB * vbB.x;
            acc[g][5] += pA * vbA.y + pB * vbB.y;
            acc[g][6] += pA * vbA.z + pB * vbB.z;
            acc[g][7] += pA * vbA.w + pB * vbB.w;
        }
    }

#pragma unroll
    for (int o = 8; o <= 16; o <<= 1) {
#pragma unroll
        for (int g = 0; g < GQ; g++) {
#pragma unroll
            for (int d = 0; d < 8; d++)
                acc[g][d] += __shfl_xor_sync(0xffffffffu, acc[g][d], o);
            l[g] += __shfl_xor_sync(0xffffffffu, l[g], o);
        }
    }

    __shared__ float s_l[4][GQ], s_acc[4][GQ][HD];
    if (tok == 0) {
#pragma unroll
        for (int g = 0; g < GQ; g++)
#pragma unroll
            for (int d = 0; d < 8; d++) s_acc[wid][g][dc * 8 + d] = acc[g][d];
    }
    if (lane == 0) {
#pragma unroll
        for (int g = 0; g < GQ; g++) s_l[wid][g] = l[g];
    }
    __syncthreads();
    int pidx = (b * NKV + kvh) * NSPLIT + sp;
    for (int p = tid; p < GQ * HD; p += 128) {
        int g = p >> 6, d = p & 63;
        float L = s_l[0][g] + s_l[1][g] + s_l[2][g] + s_l[3][g];
        float A = s_acc[0][g][d] + s_acc[1][g][d] + s_acc[2][g][d] + s_acc[3][g][d];
        g_pacc[pidx * 256 + p] = A;
        if (d == 0) g_pl[pidx * GQ + g] = L;
    }
}

__global__ __launch_bounds__(256) void attn_combine_kernel()
{
    int bk = blockIdx.x;
    int t = threadIdx.x;
    int g = t >> 6, d = t & 63;
    float L = 0.f, A = 0.f;
#pragma unroll
    for (int sp = 0; sp < NSPLIT; sp++) {
        L += g_pl[(bk * NSPLIT + sp) * GQ + g];
        A += g_pacc[(bk * NSPLIT + sp) * 256 + t];
    }
    int b = bk >> 3, kvh = bk & 7;
    g_attn[b * H + (kvh * GQ + g) * HD + d] = A / L;
}

// ---------------- launcher ----------------
static float* sym(const void* s) { void* p = nullptr; cudaGetSymbolAddress(&p, s); return (float*)p; }

extern "C" void kernel_launch(void* const* d_in, const int* in_sizes, int n_in,
                              void* d_out, int out_size)
{
    const float* x   = (const float*)d_in[0];
    const float* kc  = (const float*)d_in[1];
    const float* vc  = (const float*)d_in[2];
    const float* ln1 = (const float*)d_in[3];
    const float* qw  = (const float*)d_in[4];
    const float* kw  = (const float*)d_in[5];
    const float* vw  = (const float*)d_in[6];
    const float* ow  = (const float*)d_in[7];
    const float* ln2 = (const float*)d_in[8];
    const float* gw  = (const float*)d_in[9];
    const float* uw  = (const float*)d_in[10];
    const float* dw  = (const float*)d_in[11];
    const int*   bt  = (const int*)d_in[12];
    const int*   sl  = (const int*)d_in[13];
    float* out = (float*)d_out;

    float* a_normed = sym(g_normed);
    float* a_attn   = sym(g_attn);
    float* a_x1     = sym(g_x1);
    float* a_n2     = sym(g_n2);
    float* a_act    = sym(g_act);
    float* a_po     = sym(p_o);
    float* a_pd     = sym(p_d);

    // 1. RMSNorm 1
    rmsnorm_kernel<<<BQ, 256>>>(x, ln1, a_normed);
    // 2. QKV projection (async pipeline, 32 k-splits) + reduce w/ RoPE
    qkv_async<<<dim3(12, 32), 128>>>(qw, kw, vw);
    qkv_reduce_rope<<<192, 256>>>(sl);
    // 3. split-KV attention (8 splits)
    attn_kernel<<<dim3(NSPLIT, NKV, BQ), 128>>>(kc, vc, bt, sl);
    attn_combine_kernel<<<BQ * NKV, 256>>>();
    // 4. O projection + residual (256 blocks)
    gemm_async<<<dim3(8, 32), 128>>>(a_attn, H, ow, H, a_po);
    reduce_kernel<<<(BQ * H) / 256, 256>>>(a_po, BQ * H, 32, x, a_x1);
    // 5. RMSNorm 2
    rmsnorm_kernel<<<BQ, 256>>>(a_x1, ln2, a_n2);
    // 6. gate + up fused in ONE launch (2048 blocks), then SiLU
    gu_async<<<dim3(64, 32), 128>>>(gw, uw);
    gu_reduce_kernel<<<(BQ * INTER) / 256, 256>>>();
    // 7. down projection + residual -> out (1024 blocks)
    gemm_async<<<dim3(8, 128), 128>>>(a_act, INTER, dw, H, a_pd);
    reduce_kernel<<<(BQ * H) / 256, 256>>>(a_pd, BQ * H, 128, a_x1, out);
}

// round 17
// speedup vs baseline: 1.7023x; 1.0147x over previous
#include <cuda_runtime.h>
#include <math.h>

// ---------------- problem constants ----------------
#define BQ 32
#define H 2048
#define NH 32
#define NKV 8
#define HD 64
#define GQ 4
#define INTER 8192
#define NBLK 256
#define BSZ 16
#define NSPLIT 8
#define SPLIT_LEN 512

typedef unsigned long long ull;

#define FFMA2(d, a, b, c) \
    asm("fma.rn.f32x2 %0, %1, %2, %3;" : "=l"(d) : "l"(a), "l"(b), "l"(c))

#define CP8(dst, src) \
    asm volatile("cp.async.ca.shared.global [%0], [%1], 8;" :: "r"(dst), "l"(src))
#define CP_COMMIT() asm volatile("cp.async.commit_group;")
#define CP_WAIT2()  asm volatile("cp.async.wait_group 2;" ::: "memory")

// one 8-k chunk (2-col variant; expects smA, acc in scope; smA row stride 64)
#define FFMA_CHUNK64(kk0, wbuf)                                                      \
    _Pragma("unroll")                                                                \
    for (int b = 0; b < 32; b++) {                                                   \
        const ulonglong2* ap = reinterpret_cast<const ulonglong2*>(&smA[b * 64 + (kk0)]); \
        ulonglong2 a01 = ap[0], a23 = ap[1], a45 = ap[2], a67 = ap[3];               \
        FFMA2(acc[b], a01.x, wbuf[0], acc[b]);                                       \
        FFMA2(acc[b], a01.y, wbuf[1], acc[b]);                                       \
        FFMA2(acc[b], a23.x, wbuf[2], acc[b]);                                       \
        FFMA2(acc[b], a23.y, wbuf[3], acc[b]);                                       \
        FFMA2(acc[b], a45.x, wbuf[4], acc[b]);                                       \
        FFMA2(acc[b], a45.y, wbuf[5], acc[b]);                                       \
        FFMA2(acc[b], a67.x, wbuf[6], acc[b]);                                       \
        FFMA2(acc[b], a67.y, wbuf[7], acc[b]);                                       \
    }

// One self-contained KC=64 tile pipeline against weight base WjT.
// All smA/smW offsets compile-time static. Each thread cp.asyncs and reads
// ONLY its own smem slots -> no barriers needed inside. Leaves <=3 groups pending.
// Expects: smA loaded+synced for this tile, wsm[4], acc[32], t, n in scope.
#define GEMM_TILE(WjT)                                                               \
    _Pragma("unroll")                                                                \
    for (int c = 0; c < 3; c++) {                                                    \
        _Pragma("unroll")                                                            \
        for (int r = 0; r < 8; r++)                                                  \
            CP8(wsm[c] + r * 1024, (WjT) + (size_t)(c * 8 + r) * n);                 \
        CP_COMMIT();                                                                 \
    }                                                                                \
    _Pragma("unroll")                                                                \
    for (int c = 0; c < 8; c++) {                                                    \
        CP_WAIT2();                                                                  \
        ull w[8];                                                                    \
        const float* wp = &smW[c & 3][0][2 * t];                                     \
        _Pragma("unroll")                                                            \
        for (int r = 0; r < 8; r++)                                                  \
            w[r] = *reinterpret_cast<const ull*>(wp + r * 256);                      \
        FFMA_CHUNK64(c * 8, w)                                                       \
        if (c + 3 < 8) {                                                             \
            _Pragma("unroll")                                                        \
            for (int r = 0; r < 8; r++)                                              \
                CP8(wsm[(c + 3) & 3] + r * 1024, (WjT) + (size_t)((c + 3) * 8 + r) * n);\
            CP_COMMIT();                                                             \
        } else {                                                                     \
            CP_COMMIT();                                                             \
        }                                                                            \
    }

// smA tile load (duplicated f32x2 pairs), with pre/post barriers.
#define LOAD_SMA(Abase, LDA, KT)                                                     \
    _Pragma("unroll")                                                                \
    for (int i = t; i < 2048; i += 128) {                                            \
        int b = i >> 6, kk = i & 63;                                                 \
        unsigned r = __float_as_uint((Abase)[b * (LDA) + (KT) + kk]);                \
        smA[i] = (ull)r | ((ull)r << 32);                                            \
    }                                                                                \
    __syncthreads();

// ---------------- scratch ----------------
__device__ float g_normed[BQ * H];
__device__ float g_qkv[BQ * 3072];       // q[2048] | k[512] | v[512]
__device__ float g_attn[BQ * H];
__device__ float g_x1[BQ * H];
__device__ float g_n2[BQ * H];
__device__ float g_act[BQ * INTER];
__device__ float g_pacc[BQ * NKV * NSPLIT * GQ * HD];
__device__ float g_pl[BQ * NKV * NSPLIT * GQ];
__device__ float p_qkv[32 * BQ * 3072];
__device__ float p_o[32 * BQ * 2048];
__device__ float p_g[16 * BQ * INTER];
__device__ float p_u[16 * BQ * INTER];
__device__ float p_d[64 * BQ * 2048];

// ---------------- RMSNorm ----------------
__global__ __launch_bounds__(256) void rmsnorm_kernel(
    const float* __restrict__ x, const float* __restrict__ w, float* __restrict__ o)
{
    int b = blockIdx.x, t = threadIdx.x;
    const float* xr = x + b * H;
    float ss = 0.f;
    for (int i = t; i < H; i += 256) { float v = xr[i]; ss += v * v; }
    __shared__ float red[256];
    red[t] = ss; __syncthreads();
    for (int s = 128; s > 0; s >>= 1) {
        if (t < s) red[t] += red[t + s];
        __syncthreads();
    }
    float inv = rsqrtf(red[0] / (float)H + 1e-5f);
    for (int i = t; i < H; i += 256) o[b * H + i] = xr[i] * inv * w[i];
}

// ---------------- multi-tile 2-col GEMM partial (tile loop, static body) ----------
// grid (n/256, K/(64*NT)). acc carried across NT tiles; body code shared per tile.
template<int NT>
__global__ __launch_bounds__(128) void gemm_nt(
    const float* __restrict__ A, int lda,
    const float* __restrict__ W, int n,
    float* __restrict__ P)
{
    __shared__ ull smA[2048];
    __shared__ float smW[4][8][256];
    int t = threadIdx.x;
    int j = blockIdx.x * 256 + 2 * t;
    int kbase = blockIdx.y * (64 * NT);

    unsigned wsm[4];
#pragma unroll
    for (int s = 0; s < 4; s++)
        wsm[s] = (unsigned)__cvta_generic_to_shared(&smW[s][0][2 * t]);
    ull acc[32];
#pragma unroll
    for (int b = 0; b < 32; b++) acc[b] = 0ull;

#pragma unroll 1
    for (int tt = 0; tt < NT; tt++) {
        if (tt) __syncthreads();
        int kt = kbase + tt * 64;
        LOAD_SMA(A, lda, kt)
        const float* WjT = W + (size_t)kt * n + j;
        GEMM_TILE(WjT)
    }

    float* Pp = P + (size_t)blockIdx.y * (32 * n);
#pragma unroll
    for (int b = 0; b < 32; b++) {
        float2 v;
        v.x = __uint_as_float((unsigned)acc[b]);
        v.y = __uint_as_float((unsigned)(acc[b] >> 32));
        *reinterpret_cast<float2*>(&Pp[b * n + j]) = v;
    }
}

// ---------------- fused gate+up multi-tile partial (NT=2, one launch) ------------
// grid (64, 16): x<32 -> gate into p_g, else up into p_u. n = INTER.
__global__ __launch_bounds__(128) void gu_nt(
    const float* __restrict__ gw, const float* __restrict__ uw)
{
    __shared__ ull smA[2048];
    __shared__ float smW[4][8][256];
    int t = threadIdx.x;
    int bx = blockIdx.x;
    const float* W;
    float* P;
    int jb;
    if (bx < 32) { W = gw; P = p_g; jb = bx * 256; }
    else         { W = uw; P = p_u; jb = (bx - 32) * 256; }
    int j = jb + 2 * t;
    const int n = INTER;
    int kbase = blockIdx.y * 128;

    unsigned wsm[4];
#pragma unroll
    for (int s = 0; s < 4; s++)
        wsm[s] = (unsigned)__cvta_generic_to_shared(&smW[s][0][2 * t]);
    ull acc[32];
#pragma unroll
    for (int b = 0; b < 32; b++) acc[b] = 0ull;

#pragma unroll 1
    for (int tt = 0; tt < 2; tt++) {
        if (tt) __syncthreads();
        int kt = kbase + tt * 64;
        LOAD_SMA(g_n2, H, kt)
        const float* WjT = W + (size_t)kt * n + j;
        GEMM_TILE(WjT)
    }

    float* Pp = P + (size_t)blockIdx.y * (32 * n);
#pragma unroll
    for (int b = 0; b < 32; b++) {
        float2 v;
        v.x = __uint_as_float((unsigned)acc[b]);
        v.y = __uint_as_float((unsigned)(acc[b] >> 32));
        *reinterpret_cast<float2*>(&Pp[b * n + j]) = v;
    }
}

// ---------------- QKV fused async partial (q/k/v segments), NT=1 ----------------
__global__ __launch_bounds__(128) void qkv_async(
    const float* __restrict__ qw, const float* __restrict__ kw, const float* __restrict__ vw)
{
    __shared__ ull smA[2048];
    __shared__ float smW[4][8][256];
    int t = threadIdx.x;
    int j0 = blockIdx.x * 256;
    int kbase = blockIdx.y * 64;
    const float* W; int n; int jl;
    if (j0 < 2048)      { W = qw; n = 2048; jl = j0; }
    else if (j0 < 2560) { W = kw; n = 512;  jl = j0 - 2048; }
    else                { W = vw; n = 512;  jl = j0 - 2560; }
    jl += 2 * t;

    unsigned wsm[4];
#pragma unroll
    for (int s = 0; s < 4; s++)
        wsm[s] = (unsigned)__cvta_generic_to_shared(&smW[s][0][2 * t]);
    ull acc[32];
#pragma unroll
    for (int b = 0; b < 32; b++) acc[b] = 0ull;

    LOAD_SMA(g_normed, H, kbase)
    const float* WjT = W + (size_t)kbase * n + jl;
    GEMM_TILE(WjT)

    float* P = p_qkv + (size_t)blockIdx.y * (32 * 3072);
#pragma unroll
    for (int b = 0; b < 32; b++) {
        float2 v;
        v.x = __uint_as_float((unsigned)acc[b]);
        v.y = __uint_as_float((unsigned)(acc[b] >> 32));
        *reinterpret_cast<float2*>(&P[b * 3072 + j0 + 2 * t]) = v;
    }
}

// ---------------- fused QKV reduce + RoPE (32 partials) ----------------
__global__ __launch_bounds__(256) void qkv_reduce_rope(const int* __restrict__ sl)
{
    int idx = blockIdx.x * 256 + threadIdx.x;
    int b = idx / 1536, slot = idx - b * 1536;
    if (slot < 1280) {
        int head = slot >> 5, i = slot & 31;
        int col1 = (head < 32) ? head * 64 + i : 2048 + (head - 32) * 64 + i;
        int col2 = col1 + 32;
        float x1 = 0.f, x2 = 0.f;
#pragma unroll 4
        for (int s = 0; s < 32; s++) {
            const float* P = p_qkv + (size_t)s * (32 * 3072) + b * 3072;
            x1 += P[col1]; x2 += P[col2];
        }
        float pos = (float)sl[b];
        float inv = expf(-(float)i * (9.210340371976184f / 32.f));
        float ang = pos * inv;
        float sn, cs; sincosf(ang, &sn, &cs);
        g_qkv[b * 3072 + col1] = x1 * cs - x2 * sn;
        g_qkv[b * 3072 + col2] = x2 * cs + x1 * sn;
    } else {
        int col = 2560 + (slot - 1280) * 2;
        float a = 0.f, c = 0.f;
#pragma unroll 4
        for (int s = 0; s < 32; s++) {
            const float* P = p_qkv + (size_t)s * (32 * 3072) + b * 3072;
            a += P[col]; c += P[col + 1];
        }
        g_qkv[b * 3072 + col] = a;
        g_qkv[b * 3072 + col + 1] = c;
    }
}

// ---------------- reduces ----------------
__global__ void reduce_kernel(const float* __restrict__ P, int total, int KS,
                              const float* __restrict__ res, float* __restrict__ out)
{
    int i = blockIdx.x * 256 + threadIdx.x;
    if (i >= total) return;
    float v = res ? res[i] : 0.f;
#pragma unroll 8
    for (int s = 0; s < KS; s++) v += P[(size_t)s * total + i];
    out[i] = v;
}

__global__ void gu_reduce_kernel()
{
    int i = blockIdx.x * 256 + threadIdx.x;
    const int total = BQ * INTER;
    float gv = 0.f, uv = 0.f;
#pragma unroll 8
    for (int s = 0; s < 16; s++) {
        gv += p_g[(size_t)s * total + i];
        uv += p_u[(size_t)s * total + i];
    }
    g_act[i] = gv * (1.f / (1.f + __expf(-gv))) * uv;
}

// ---------------- split-KV decode attention (smem bt, fixed-ref softmax, 2x unroll) ----
__global__ __launch_bounds__(128) void attn_kernel(
    const float* __restrict__ kc, const float* __restrict__ vc,
    const int* __restrict__ bt, const int* __restrict__ sl)
{
    int sp = blockIdx.x, kvh = blockIdx.y, b = blockIdx.z;
    int tid = threadIdx.x, wid = tid >> 5, lane = tid & 31;
    int dc = lane & 7, tok = lane >> 3;
    int seqlen = sl[b];
    int total = seqlen + 1;
    int start = sp * SPLIT_LEN;
    int end = min(start + SPLIT_LEN, total);

    __shared__ int s_bt[SPLIT_LEN / BSZ];   // 32 block entries for this split
    if (tid < SPLIT_LEN / BSZ)
        s_bt[tid] = bt[b * NBLK + sp * (SPLIT_LEN / BSZ) + tid];
    __syncthreads();
    int btbase = sp * (SPLIT_LEN / BSZ);

    float4 qa[GQ], qb[GQ];
#pragma unroll
    for (int g = 0; g < GQ; g++) {
        const float* qp = g_qkv + b * 3072 + (kvh * GQ + g) * HD + dc * 8;
        float4 a = *reinterpret_cast<const float4*>(qp);
        float4 c = *reinterpret_cast<const float4*>(qp + 4);
        a.x *= 0.125f; a.y *= 0.125f; a.z *= 0.125f; a.w *= 0.125f;
        c.x *= 0.125f; c.y *= 0.125f; c.z *= 0.125f; c.w *= 0.125f;
        qa[g] = a; qb[g] = c;
    }
    float l[GQ], acc[GQ][8];
#pragma unroll
    for (int g = 0; g < GQ; g++) {
        l[g] = 0.f;
#pragma unroll
        for (int d = 0; d < 8; d++) acc[g][d] = 0.f;
    }

    for (int s0 = start + wid * 4; s0 < end; s0 += 32) {
        int sA = s0 + tok;
        int sB = s0 + 16 + tok;
        bool vA = sA < end, vB = sB < end;
        float4 kaA = {0,0,0,0}, kbA = {0,0,0,0}, vaA = {0,0,0,0}, vbA = {0,0,0,0};
        float4 kaB = {0,0,0,0}, kbB = {0,0,0,0}, vaB = {0,0,0,0}, vbB = {0,0,0,0};
        if (vA) {
            const float *kp, *vp;
            if (sA == seqlen) {
                kp = g_qkv + b * 3072 + 2048 + kvh * HD;
                vp = kp + 512;
            } else {
                int blk = s_bt[(sA >> 4) - btbase];
                int off = ((blk * BSZ + (sA & 15)) * NKV + kvh) * HD;
                kp = kc + off; vp = vc + off;
            }
            kaA = *reinterpret_cast<const float4*>(kp + dc * 8);
            kbA = *reinterpret_cast<const float4*>(kp + dc * 8 + 4);
            vaA = *reinterpret_cast<const float4*>(vp + dc * 8);
            vbA = *reinterpret_cast<const float4*>(vp + dc * 8 + 4);
        }
        if (vB) {
            const float *kp, *vp;
            if (sB == seqlen) {
                kp = g_qkv + b * 3072 + 2048 + kvh * HD;
                vp = kp + 512;
            } else {
                int blk = s_bt[(sB >> 4) - btbase];
                int off = ((blk * BSZ + (sB & 15)) * NKV + kvh) * HD;
                kp = kc + off; vp = vc + off;
            }
            kaB = *reinterpret_cast<const float4*>(kp + dc * 8);
            kbB = *reinterpret_cast<const float4*>(kp + dc * 8 + 4);
            vaB = *reinterpret_cast<const float4*>(vp + dc * 8);
            vbB = *reinterpret_cast<const float4*>(vp + dc * 8 + 4);
        }
        float scA[GQ], scB[GQ];
#pragma unroll
        for (int g = 0; g < GQ; g++) {
            scA[g] = qa[g].x * kaA.x + qa[g].y * kaA.y + qa[g].z * kaA.z + qa[g].w * kaA.w
                   + qb[g].x * kbA.x + qb[g].y * kbA.y + qb[g].z * kbA.z + qb[g].w * kbA.w;
            scB[g] = qa[g].x * kaB.x + qa[g].y * kaB.y + qa[g].z * kaB.z + qa[g].w * kaB.w
                   + qb[g].x * kbB.x + qb[g].y * kbB.y + qb[g].z * kbB.z + qb[g].w * kbB.w;
        }
#pragma unroll
        for (int o = 1; o <= 4; o <<= 1) {
#pragma unroll
            for (int g = 0; g < GQ; g++) {
                scA[g] += __shfl_xor_sync(0xffffffffu, scA[g], o);
                scB[g] += __shfl_xor_sync(0xffffffffu, scB[g], o);
            }
        }
#pragma unroll
        for (int g = 0; g < GQ; g++) {
            float pA = vA ? __expf(fminf(scA[g], 75.f)) : 0.f;
            float pB = vB ? __expf(fminf(scB[g], 75.f)) : 0.f;
            l[g] += pA + pB;
            acc[g][0] += pA * vaA.x + pB * vaB.x;
            acc[g][1] += pA * vaA.y + pB * vaB.y;
            acc[g][2] += pA * vaA.z + pB * vaB.z;
            acc[g][3] += pA * vaA.w + pB * vaB.w;
            acc[g][4] += pA * vbA.x + pB * vbB.x;
            acc[g][5] += pA * vbA.y + pB * vbB.y;
            acc[g][6] += pA * vbA.z + pB * vbB.z;
            acc[g][7] += pA * vbA.w + pB * vbB.w;
        }
    }

#pragma unroll
    for (int o = 8; o <= 16; o <<= 1) {
#pragma unroll
        for (int g = 0; g < GQ; g++) {
#pragma unroll
            for (int d = 0; d < 8; d++)
                acc[g][d] += __shfl_xor_sync(0xffffffffu, acc[g][d], o);
            l[g] += __shfl_xor_sync(0xffffffffu, l[g], o);
        }
    }

    __shared__ float s_l[4][GQ], s_acc[4][GQ][HD];
    if (tok == 0) {
#pragma unroll
        for (int g = 0; g < GQ; g++)
#pragma unroll
            for (int d = 0; d < 8; d++) s_acc[wid][g][dc * 8 + d] = acc[g][d];
    }
    if (lane == 0) {
#pragma unroll
        for (int g = 0; g < GQ; g++) s_l[wid][g] = l[g];
    }
    __syncthreads();
    int pidx = (b * NKV + kvh) * NSPLIT + sp;
    for (int p = tid; p < GQ * HD; p += 128) {
        int g = p >> 6, d = p & 63;
        float L = s_l[0][g] + s_l[1][g] + s_l[2][g] + s_l[3][g];
        float A = s_acc[0][g][d] + s_acc[1][g][d] + s_acc[2][g][d] + s_acc[3][g][d];
        g_pacc[pidx * 256 + p] = A;
        if (d == 0) g_pl[pidx * GQ + g] = L;
    }
}

__global__ __launch_bounds__(256) void attn_combine_kernel()
{
    int bk = blockIdx.x;
    int t = threadIdx.x;
    int g = t >> 6, d = t & 63;
    float L = 0.f, A = 0.f;
#pragma unroll
    for (int sp = 0; sp < NSPLIT; sp++) {
        L += g_pl[(bk * NSPLIT + sp) * GQ + g];
        A += g_pacc[(bk * NSPLIT + sp) * 256 + t];
    }
    int b = bk >> 3, kvh = bk & 7;
    g_attn[b * H + (kvh * GQ + g) * HD + d] = A / L;
}

// ---------------- launcher ----------------
static float* sym(const void* s) { void* p = nullptr; cudaGetSymbolAddress(&p, s); return (float*)p; }

extern "C" void kernel_launch(void* const* d_in, const int* in_sizes, int n_in,
                              void* d_out, int out_size)
{
    const float* x   = (const float*)d_in[0];
    const float* kc  = (const float*)d_in[1];
    const float* vc  = (const float*)d_in[2];
    const float* ln1 = (const float*)d_in[3];
    const float* qw  = (const float*)d_in[4];
    const float* kw  = (const float*)d_in[5];
    const float* vw  = (const float*)d_in[6];
    const float* ow  = (const float*)d_in[7];
    const float* ln2 = (const float*)d_in[8];
    const float* gw  = (const float*)d_in[9];
    const float* uw  = (const float*)d_in[10];
    const float* dw  = (const float*)d_in[11];
    const int*   bt  = (const int*)d_in[12];
    const int*   sl  = (const int*)d_in[13];
    float* out = (float*)d_out;

    float* a_normed = sym(g_normed);
    float* a_attn   = sym(g_attn);
    float* a_x1     = sym(g_x1);
    float* a_n2     = sym(g_n2);
    float* a_act    = sym(g_act);
    float* a_po     = sym(p_o);
    float* a_pd     = sym(p_d);

    // 1. RMSNorm 1
    rmsnorm_kernel<<<BQ, 256>>>(x, ln1, a_normed);
    // 2. QKV projection (32 k-splits) + reduce w/ RoPE
    qkv_async<<<dim3(12, 32), 128>>>(qw, kw, vw);
    qkv_reduce_rope<<<192, 256>>>(sl);
    // 3. split-KV attention (8 splits)
    attn_kernel<<<dim3(NSPLIT, NKV, BQ), 128>>>(kc, vc, bt, sl);
    attn_combine_kernel<<<BQ * NKV, 256>>>();
    // 4. O projection + residual (NT=1, 256 blocks)
    gemm_nt<1><<<dim3(8, 32), 128>>>(a_attn, H, ow, H, a_po);
    reduce_kernel<<<(BQ * H) / 256, 256>>>(a_po, BQ * H, 32, x, a_x1);
    // 5. RMSNorm 2
    rmsnorm_kernel<<<BQ, 256>>>(a_x1, ln2, a_n2);
    // 6. gate + up fused, NT=2 (16 splits, 1024 blocks), then SiLU
    gu_nt<<<dim3(64, 16), 128>>>(gw, uw);
    gu_reduce_kernel<<<(BQ * INTER) / 256, 256>>>();
    // 7. down projection NT=2 (64 splits, 512 blocks) + residual -> out
    gemm_nt<2><<<dim3(8, 64), 128>>>(a_act, INTER, dw, H, a_pd);
    reduce_kernel<<<(BQ * H) / 256, 256>>>(a_pd, BQ * H, 64, a_x1, out);
}